// round 2
// baseline (speedup 1.0000x reference)
#include <cuda_runtime.h>

#define S 2048
#define HID 2048
#define NH 16
#define NKV 2
#define HD 128
#define NREP 8
#define SCALE 0.08838834764831845f

// ---------------- scratch (__device__ globals; no allocs allowed) ----------------
__device__ float g_qp[S * NH * HD];            // Q proj  [S, 2048]
__device__ float g_kp[S * NKV * HD];           // K proj  [S, 256]
__device__ float g_vp[S * NKV * HD];           // V proj  [S, 256]
__device__ float g_q [NH * S * HD];            // RoPE'd Q [H, S, D]
__device__ float g_k [NKV * S * HD];           // RoPE'd K [KVH, S, D]
__device__ float g_sc[(long long)NH * S * S];  // scores/probs [H, S, S] (256 MB)
__device__ float g_ao[S * NH * HD];            // attn out [S, 2048]

// ---------------- generic batched strided GEMM ----------------
// C[bz] = alpha * A[bz] @ (B[bz/bDiv] or B^T) + bias
// causal: 0 = none, 1 = skip tiles with bx > by (scores), 2 = clamp K to rowTileEnd (PV)
#define BM 64
#define BN 64
#define BK 16

__global__ __launch_bounds__(256) void gemm_kernel(
    const float* __restrict__ A, const float* __restrict__ B,
    const float* __restrict__ bias, float* __restrict__ C,
    int M, int N, int K,
    int lda, int ldb, int ldc,
    long long sA, long long sB, long long sC, int bDiv,
    int transB, float alpha, int causal)
{
    int bx = blockIdx.x, by = blockIdx.y, bz = blockIdx.z;
    if (causal == 1 && bx > by) return;

    const float* Ab = A + (long long)bz * sA;
    const float* Bb = B + (long long)(bz / bDiv) * sB;
    float*       Cb = C + (long long)bz * sC;

    __shared__ float As[BK][BM];
    __shared__ float Bs[BK][BN + 1];

    int tid = threadIdx.x;
    int tx = tid & 15, ty = tid >> 4;
    int rowBase = by * BM, colBase = bx * BN;

    float acc[4][4] = {};

    int Klim = (causal == 2) ? min(K, rowBase + BM) : K;

    // A loader indices: each thread loads float4 along K
    int aRow = tid >> 2;            // 0..63
    int aK4  = (tid & 3) << 2;      // 0,4,8,12

    for (int k0 = 0; k0 < Klim; k0 += BK) {
        float4 av = *(const float4*)&Ab[(long long)(rowBase + aRow) * lda + k0 + aK4];
        As[aK4 + 0][aRow] = av.x;
        As[aK4 + 1][aRow] = av.y;
        As[aK4 + 2][aRow] = av.z;
        As[aK4 + 3][aRow] = av.w;

        if (!transB) {
            int bK  = tid >> 4;             // 0..15
            int bN4 = (tid & 15) << 2;      // 0..60
            float4 bv = *(const float4*)&Bb[(long long)(k0 + bK) * ldb + colBase + bN4];
            Bs[bK][bN4 + 0] = bv.x;
            Bs[bK][bN4 + 1] = bv.y;
            Bs[bK][bN4 + 2] = bv.z;
            Bs[bK][bN4 + 3] = bv.w;
        } else {
            int bN  = tid >> 2;             // 0..63
            int bK4 = (tid & 3) << 2;       // 0,4,8,12
            float4 bv = *(const float4*)&Bb[(long long)(colBase + bN) * ldb + k0 + bK4];
            Bs[bK4 + 0][bN] = bv.x;
            Bs[bK4 + 1][bN] = bv.y;
            Bs[bK4 + 2][bN] = bv.z;
            Bs[bK4 + 3][bN] = bv.w;
        }
        __syncthreads();

        #pragma unroll
        for (int k = 0; k < BK; k++) {
            float a0 = As[k][ty * 4 + 0];
            float a1 = As[k][ty * 4 + 1];
            float a2 = As[k][ty * 4 + 2];
            float a3 = As[k][ty * 4 + 3];
            float b0 = Bs[k][tx * 4 + 0];
            float b1 = Bs[k][tx * 4 + 1];
            float b2 = Bs[k][tx * 4 + 2];
            float b3 = Bs[k][tx * 4 + 3];
            acc[0][0] += a0 * b0; acc[0][1] += a0 * b1; acc[0][2] += a0 * b2; acc[0][3] += a0 * b3;
            acc[1][0] += a1 * b0; acc[1][1] += a1 * b1; acc[1][2] += a1 * b2; acc[1][3] += a1 * b3;
            acc[2][0] += a2 * b0; acc[2][1] += a2 * b1; acc[2][2] += a2 * b2; acc[2][3] += a2 * b3;
            acc[3][0] += a3 * b0; acc[3][1] += a3 * b1; acc[3][2] += a3 * b2; acc[3][3] += a3 * b3;
        }
        __syncthreads();
    }

    #pragma unroll
    for (int i = 0; i < 4; i++) {
        int m = rowBase + ty * 4 + i;
        #pragma unroll
        for (int j = 0; j < 4; j++) {
            int n = colBase + tx * 4 + j;
            float v = acc[i][j] * alpha;
            if (bias) v += bias[n];
            Cb[(long long)m * ldc + n] = v;
        }
    }
}

// ---------------- RoPE + transpose to head-major ----------------
// q: [S, H*D] -> g_q [H, S, D]; k: [S, KVH*D] -> g_k [KVH, S, D]
__global__ void rope_kernel(const float* __restrict__ qp, const float* __restrict__ kp,
                            const float* __restrict__ cs, const float* __restrict__ sn)
{
    int idx = blockIdx.x * blockDim.x + threadIdx.x;  // (NH+NKV)*S*HD threads
    int d = idx & (HD - 1);
    int s = (idx >> 7) & (S - 1);
    int h = idx >> 18;   // 0..17

    float c  = cs[(s << 7) + d];
    float si = sn[(s << 7) + d];

    if (h < NH) {
        const float* row = qp + (long long)s * (NH * HD) + h * HD;
        float x = row[d];
        float r = (d < 64) ? -row[d + 64] : row[d - 64];
        g_q[((long long)h * S + s) * HD + d] = x * c + r * si;
    } else {
        int hk = h - NH;
        const float* row = kp + (long long)s * (NKV * HD) + hk * HD;
        float x = row[d];
        float r = (d < 64) ? -row[d + 64] : row[d - 64];
        g_k[((long long)hk * S + s) * HD + d] = x * c + r * si;
    }
}

// ---------------- causal row softmax (in-place on g_sc) ----------------
// One block per (row, head). Zeroes masked tail up to the next 64-boundary so
// the PV gemm can clamp its K loop at the row tile end.
__global__ __launch_bounds__(256) void softmax_kernel()
{
    int i = blockIdx.x;   // query row
    int h = blockIdx.y;   // head
    float* row = g_sc + ((long long)h * S + i) * S;
    int L = i + 1;
    int tid = threadIdx.x;
    __shared__ float red[256];

    float m = -1e30f;
    for (int j = tid; j < L; j += 256) m = fmaxf(m, row[j]);
    red[tid] = m; __syncthreads();
    for (int s2 = 128; s2 > 0; s2 >>= 1) {
        if (tid < s2) red[tid] = fmaxf(red[tid], red[tid + s2]);
        __syncthreads();
    }
    m = red[0]; __syncthreads();

    float sum = 0.f;
    for (int j = tid; j < L; j += 256) sum += __expf(row[j] - m);
    red[tid] = sum; __syncthreads();
    for (int s2 = 128; s2 > 0; s2 >>= 1) {
        if (tid < s2) red[tid] += red[tid + s2];
        __syncthreads();
    }
    float inv = 1.0f / red[0];

    int Lpad = ((i >> 6) + 1) << 6;   // zero to end of 64-row tile
    for (int j = tid; j < Lpad; j += 256)
        row[j] = (j < L) ? __expf(row[j] - m) * inv : 0.f;
}

// ---------------- launch ----------------
extern "C" void kernel_launch(void* const* d_in, const int* in_sizes, int n_in,
                              void* d_out, int out_size)
{
    const float* hidden = (const float*)d_in[0];
    const float* cosb   = (const float*)d_in[1];
    const float* sinb   = (const float*)d_in[2];
    // d_in[3] attention_mask: pure causal, handled analytically
    const float* Wq = (const float*)d_in[4];
    const float* bq = (const float*)d_in[5];
    const float* Wk = (const float*)d_in[6];
    const float* bk = (const float*)d_in[7];
    const float* Wv = (const float*)d_in[8];
    const float* bv = (const float*)d_in[9];
    const float* Wo = (const float*)d_in[10];
    float* out = (float*)d_out;

    float *qp, *kp, *vp, *q, *k, *sc, *ao;
    cudaGetSymbolAddress((void**)&qp, g_qp);
    cudaGetSymbolAddress((void**)&kp, g_kp);
    cudaGetSymbolAddress((void**)&vp, g_vp);
    cudaGetSymbolAddress((void**)&q,  g_q);
    cudaGetSymbolAddress((void**)&k,  g_k);
    cudaGetSymbolAddress((void**)&sc, g_sc);
    cudaGetSymbolAddress((void**)&ao, g_ao);

    // 1) projections
    gemm_kernel<<<dim3(32, 32, 1), 256>>>(hidden, Wq, bq, qp,
        S, NH * HD, HID, HID, NH * HD, NH * HD, 0, 0, 0, 1, 0, 1.0f, 0);
    gemm_kernel<<<dim3(4, 32, 1), 256>>>(hidden, Wk, bk, kp,
        S, NKV * HD, HID, HID, NKV * HD, NKV * HD, 0, 0, 0, 1, 0, 1.0f, 0);
    gemm_kernel<<<dim3(4, 32, 1), 256>>>(hidden, Wv, bv, vp,
        S, NKV * HD, HID, HID, NKV * HD, NKV * HD, 0, 0, 0, 1, 0, 1.0f, 0);

    // 2) RoPE + transpose
    rope_kernel<<<(NH + NKV) * S * HD / 256, 256>>>(qp, kp, cosb, sinb);

    // 3) scores = scale * Q @ K^T  (batched over 16 heads, GQA via bDiv=8,
    //    causal tile skip)
    gemm_kernel<<<dim3(32, 32, NH), 256>>>(q, k, nullptr, sc,
        S, S, HD, HD, HD, S,
        (long long)S * HD, (long long)S * HD, (long long)S * S, NREP,
        1, SCALE, 1);

    // 4) softmax (causal, zero-fills masked tail of each 64-tile)
    softmax_kernel<<<dim3(S, NH), 256>>>();

    // 5) attn_out = P @ V  (batched, K-loop clamped via causal=2)
    gemm_kernel<<<dim3(2, 32, NH), 256>>>(sc, vp, nullptr, ao,
        S, HD, S, S, NKV * HD, NH * HD,
        (long long)S * S, (long long)HD, (long long)HD, NREP,
        0, 1.0f, 2);

    // 6) output projection
    gemm_kernel<<<dim3(32, 32, 1), 256>>>(ao, Wo, nullptr, out,
        S, HID, NH * HD, NH * HD, HID, HID, 0, 0, 0, 1, 0, 1.0f, 0);
}

// round 3
// speedup vs baseline: 1.4007x; 1.4007x over previous
#include <cuda_runtime.h>

#define S 2048
#define HID 2048
#define NH 16
#define NKV 2
#define HD 128
#define NREP 8
#define SCALE 0.08838834764831845f

// ---------------- scratch ----------------
__device__ float g_qp[S * NH * HD];
__device__ float g_kp[S * NKV * HD];
__device__ float g_vp[S * NKV * HD];
__device__ float g_q [NH * S * HD];
__device__ float g_k [NKV * S * HD];
__device__ float g_sc[(long long)NH * S * S];
__device__ float g_ao[S * NH * HD];

// ---------------- packed f32x2 helpers ----------------
#define FMA2(d, a, b) asm("fma.rn.f32x2 %0, %1, %2, %0;" : "+l"(d) : "l"(a), "l"(b))
#define PACK2(d, x)   asm("mov.b64 %0, {%1, %1};" : "=l"(d) : "f"(x))
#define UNPACK2(lo, hi, v) asm("mov.b64 {%0, %1}, %2;" : "=f"(lo), "=f"(hi) : "l"(v))

#define BM 128
#define BN 128
#define BK 16

// ---------------- core: one 128x128 C tile ----------------
__device__ __forceinline__ void gemm_core(
    const float* __restrict__ A, const float* __restrict__ B,
    const float* __restrict__ bias, float* __restrict__ C,
    int bx, int by, int K,
    int lda, int ldb, int ldc, int transB, float alpha)
{
    __shared__ float As[BK][BM];
    __shared__ float Bs[BK][BN];

    int tid = threadIdx.x;
    int tx = tid & 15, ty = tid >> 4;
    int rowBase = by * BM, colBase = bx * BN;

    unsigned long long acc[8][4];
    #pragma unroll
    for (int i = 0; i < 8; i++)
        #pragma unroll
        for (int j = 0; j < 4; j++) acc[i][j] = 0ull;

    for (int k0 = 0; k0 < K; k0 += BK) {
        // A tile -> As[k][m] (transposed store)
        #pragma unroll
        for (int r = 0; r < 2; r++) {
            int idx = r * 256 + tid;
            int row = idx >> 2, kq = (idx & 3) << 2;
            float4 v = *(const float4*)&A[(long long)(rowBase + row) * lda + k0 + kq];
            As[kq + 0][row] = v.x; As[kq + 1][row] = v.y;
            As[kq + 2][row] = v.z; As[kq + 3][row] = v.w;
        }
        // B tile -> Bs[k][n]
        if (!transB) {
            #pragma unroll
            for (int r = 0; r < 2; r++) {
                int idx = r * 256 + tid;
                int kr = idx >> 5, nq = (idx & 31) << 2;
                *(float4*)&Bs[kr][nq] =
                    *(const float4*)&B[(long long)(k0 + kr) * ldb + colBase + nq];
            }
        } else {
            #pragma unroll
            for (int r = 0; r < 2; r++) {
                int idx = r * 256 + tid;
                int n = idx >> 2, kq = (idx & 3) << 2;
                float4 v = *(const float4*)&B[(long long)(colBase + n) * ldb + k0 + kq];
                Bs[kq + 0][n] = v.x; Bs[kq + 1][n] = v.y;
                Bs[kq + 2][n] = v.z; Bs[kq + 3][n] = v.w;
            }
        }
        __syncthreads();

        #pragma unroll
        for (int k = 0; k < BK; k++) {
            float4 a0 = *(const float4*)&As[k][ty * 4];
            float4 a1 = *(const float4*)&As[k][64 + ty * 4];
            ulonglong2 bl0 = *(const ulonglong2*)&Bs[k][tx * 4];
            ulonglong2 bl1 = *(const ulonglong2*)&Bs[k][64 + tx * 4];
            unsigned long long bv0 = bl0.x, bv1 = bl0.y, bv2 = bl1.x, bv3 = bl1.y;
            unsigned long long ap[8];
            PACK2(ap[0], a0.x); PACK2(ap[1], a0.y); PACK2(ap[2], a0.z); PACK2(ap[3], a0.w);
            PACK2(ap[4], a1.x); PACK2(ap[5], a1.y); PACK2(ap[6], a1.z); PACK2(ap[7], a1.w);
            #pragma unroll
            for (int i = 0; i < 8; i++) {
                FMA2(acc[i][0], ap[i], bv0);
                FMA2(acc[i][1], ap[i], bv1);
                FMA2(acc[i][2], ap[i], bv2);
                FMA2(acc[i][3], ap[i], bv3);
            }
        }
        __syncthreads();
    }

    // epilogue
    #pragma unroll
    for (int i = 0; i < 8; i++) {
        int m = rowBase + ((i < 4) ? ty * 4 + i : 64 + ty * 4 + i - 4);
        float c0, c1, c2, c3;
        float4 o;

        int n0 = colBase + tx * 4;
        UNPACK2(c0, c1, acc[i][0]); UNPACK2(c2, c3, acc[i][1]);
        o.x = c0 * alpha; o.y = c1 * alpha; o.z = c2 * alpha; o.w = c3 * alpha;
        if (bias) { o.x += bias[n0]; o.y += bias[n0 + 1]; o.z += bias[n0 + 2]; o.w += bias[n0 + 3]; }
        *(float4*)&C[(long long)m * ldc + n0] = o;

        int n1 = colBase + 64 + tx * 4;
        UNPACK2(c0, c1, acc[i][2]); UNPACK2(c2, c3, acc[i][3]);
        o.x = c0 * alpha; o.y = c1 * alpha; o.z = c2 * alpha; o.w = c3 * alpha;
        if (bias) { o.x += bias[n1]; o.y += bias[n1 + 1]; o.z += bias[n1 + 2]; o.w += bias[n1 + 3]; }
        *(float4*)&C[(long long)m * ldc + n1] = o;
    }
}

// ---------------- generic batched wrapper ----------------
// causal: 0 none, 1 skip bx>by (scores), 2 clamp K to row tile end (PV)
__global__ __launch_bounds__(256) void gemm_kernel(
    const float* __restrict__ A, const float* __restrict__ B,
    const float* __restrict__ bias, float* __restrict__ C,
    int K, int lda, int ldb, int ldc,
    long long sA, long long sB, long long sC, int bDiv,
    int transB, float alpha, int causal)
{
    int bx = blockIdx.x, by = blockIdx.y, bz = blockIdx.z;
    if (causal == 1 && bx > by) return;
    int Klim = (causal == 2) ? min(K, (by + 1) * BM) : K;
    gemm_core(A + (long long)bz * sA, B + (long long)(bz / bDiv) * sB,
              bias, C + (long long)bz * sC, bx, by, Klim, lda, ldb, ldc, transB, alpha);
}

// ---------------- fused QKV projection (one launch, grid.x = 16+2+2) ----------------
__global__ __launch_bounds__(256) void qkv_kernel(
    const float* __restrict__ hidden,
    const float* __restrict__ Wq, const float* __restrict__ bq,
    const float* __restrict__ Wk, const float* __restrict__ bk,
    const float* __restrict__ Wv, const float* __restrict__ bv,
    float* __restrict__ qp, float* __restrict__ kp, float* __restrict__ vp)
{
    int bx = blockIdx.x;
    const float* B; const float* bias; float* C; int N, cb;
    if (bx < 16)      { B = Wq; bias = bq; C = qp; N = NH * HD;  cb = bx; }
    else if (bx < 18) { B = Wk; bias = bk; C = kp; N = NKV * HD; cb = bx - 16; }
    else              { B = Wv; bias = bv; C = vp; N = NKV * HD; cb = bx - 18; }
    gemm_core(hidden, B, bias, C, cb, blockIdx.y, HID, HID, N, N, 0, 1.0f);
}

// ---------------- RoPE + transpose to head-major ----------------
__global__ void rope_kernel(const float* __restrict__ qp, const float* __restrict__ kp,
                            const float* __restrict__ cs, const float* __restrict__ sn)
{
    int idx = blockIdx.x * blockDim.x + threadIdx.x;
    int d = idx & (HD - 1);
    int s = (idx >> 7) & (S - 1);
    int h = idx >> 18;

    float c  = cs[(s << 7) + d];
    float si = sn[(s << 7) + d];

    if (h < NH) {
        const float* row = qp + (long long)s * (NH * HD) + h * HD;
        float x = row[d];
        float r = (d < 64) ? -row[d + 64] : row[d - 64];
        g_q[((long long)h * S + s) * HD + d] = x * c + r * si;
    } else {
        int hk = h - NH;
        const float* row = kp + (long long)s * (NKV * HD) + hk * HD;
        float x = row[d];
        float r = (d < 64) ? -row[d + 64] : row[d - 64];
        g_k[((long long)hk * S + s) * HD + d] = x * c + r * si;
    }
}

// ---------------- causal row softmax (zero-fills tail up to 128-boundary) ----------------
__global__ __launch_bounds__(256) void softmax_kernel()
{
    int i = blockIdx.x;
    int h = blockIdx.y;
    float* row = g_sc + ((long long)h * S + i) * S;
    int L = i + 1;
    int tid = threadIdx.x;
    __shared__ float red[256];

    float m = -1e30f;
    for (int j = tid; j < L; j += 256) m = fmaxf(m, row[j]);
    red[tid] = m; __syncthreads();
    for (int s2 = 128; s2 > 0; s2 >>= 1) {
        if (tid < s2) red[tid] = fmaxf(red[tid], red[tid + s2]);
        __syncthreads();
    }
    m = red[0]; __syncthreads();

    float sum = 0.f;
    for (int j = tid; j < L; j += 256) sum += __expf(row[j] - m);
    red[tid] = sum; __syncthreads();
    for (int s2 = 128; s2 > 0; s2 >>= 1) {
        if (tid < s2) red[tid] += red[tid + s2];
        __syncthreads();
    }
    float inv = 1.0f / red[0];

    int Lpad = ((i >> 7) + 1) << 7;   // zero to end of 128-row tile (matches BM)
    for (int j = tid; j < Lpad; j += 256)
        row[j] = (j < L) ? __expf(row[j] - m) * inv : 0.f;
}

// ---------------- launch ----------------
extern "C" void kernel_launch(void* const* d_in, const int* in_sizes, int n_in,
                              void* d_out, int out_size)
{
    const float* hidden = (const float*)d_in[0];
    const float* cosb   = (const float*)d_in[1];
    const float* sinb   = (const float*)d_in[2];
    const float* Wq = (const float*)d_in[4];
    const float* bq = (const float*)d_in[5];
    const float* Wk = (const float*)d_in[6];
    const float* bk = (const float*)d_in[7];
    const float* Wv = (const float*)d_in[8];
    const float* bv = (const float*)d_in[9];
    const float* Wo = (const float*)d_in[10];
    float* out = (float*)d_out;

    float *qp, *kp, *vp, *q, *k, *sc, *ao;
    cudaGetSymbolAddress((void**)&qp, g_qp);
    cudaGetSymbolAddress((void**)&kp, g_kp);
    cudaGetSymbolAddress((void**)&vp, g_vp);
    cudaGetSymbolAddress((void**)&q,  g_q);
    cudaGetSymbolAddress((void**)&k,  g_k);
    cudaGetSymbolAddress((void**)&sc, g_sc);
    cudaGetSymbolAddress((void**)&ao, g_ao);

    // 1) fused QKV projection
    qkv_kernel<<<dim3(20, 16), 256>>>(hidden, Wq, bq, Wk, bk, Wv, bv, qp, kp, vp);

    // 2) RoPE + transpose
    rope_kernel<<<(NH + NKV) * S * HD / 256, 256>>>(qp, kp, cosb, sinb);

    // 3) scores = scale * Q @ K^T (batched heads, GQA bDiv=8, causal tile skip)
    gemm_kernel<<<dim3(16, 16, NH), 256>>>(q, k, nullptr, sc,
        HD, HD, HD, S,
        (long long)S * HD, (long long)S * HD, (long long)S * S, NREP,
        1, SCALE, 1);

    // 4) softmax
    softmax_kernel<<<dim3(S, NH), 256>>>();

    // 5) attn_out = P @ V (K-loop clamped)
    gemm_kernel<<<dim3(1, 16, NH), 256>>>(sc, vp, nullptr, ao,
        S, S, NKV * HD, NH * HD,
        (long long)S * S, (long long)HD, (long long)HD, NREP,
        0, 1.0f, 2);

    // 6) output projection
    gemm_kernel<<<dim3(16, 16, 1), 256>>>(ao, Wo, nullptr, out,
        NH * HD, NH * HD, HID, HID, 0, 0, 0, 1, 0, 1.0f, 0);
}

// round 5
// speedup vs baseline: 2.8171x; 2.0112x over previous
#include <cuda_runtime.h>
#include <cuda_bf16.h>
#include <cstdint>

typedef __nv_bfloat16 bf16;

#define S 2048
#define HID 2048
#define NH 16
#define NKV 2
#define HD 128
#define NREP 8
#define SCALE 0.08838834764831845f

// ---------------- scratch ----------------
__device__ __align__(16) bf16  g_hh[S * HID], g_hl[S * HID];
__device__ __align__(16) bf16  g_wqth[HID * HID], g_wqtl[HID * HID];   // W^T splits [N][K]
__device__ __align__(16) bf16  g_wkth[256 * HID], g_wktl[256 * HID];
__device__ __align__(16) bf16  g_wvth[256 * HID], g_wvtl[256 * HID];
__device__ __align__(16) bf16  g_woth[HID * HID], g_wotl[HID * HID];
__device__ float g_qp[S * NH * HD], g_kp[S * NKV * HD], g_vp[S * NKV * HD];
__device__ __align__(16) bf16  g_qh[NH * S * HD], g_ql[NH * S * HD];
__device__ __align__(16) bf16  g_kh[NKV * S * HD], g_kl[NKV * S * HD];
__device__ __align__(16) bf16  g_vth[NKV * HD * S], g_vtl[NKV * HD * S];  // V^T [D][S]
__device__ float g_sc[(long long)NH * S * S];
__device__ __align__(16) bf16  g_ph[(long long)NH * S * S];
__device__ __align__(16) bf16  g_pl[(long long)NH * S * S];
__device__ float g_ao[S * NH * HD];
__device__ __align__(16) bf16  g_aoh[S * NH * HD], g_aol[S * NH * HD];

// ---------------- PTX helpers (all baseline sm_80+ features) ----------------
__device__ __forceinline__ uint32_t smem_to_u32(const void* p) {
    uint32_t a;
    asm("{ .reg .u64 t; cvta.to.shared.u64 t, %1; cvt.u32.u64 %0, t; }" : "=r"(a) : "l"(p));
    return a;
}

#define CP_ASYNC16(dst, src) \
    asm volatile("cp.async.cg.shared.global [%0], [%1], 16;" :: "r"(dst), "l"(src))
#define CP_COMMIT() asm volatile("cp.async.commit_group;" ::: "memory")

__device__ __forceinline__ void ldsm_x4(uint32_t* r, uint32_t addr) {
    asm volatile("ldmatrix.sync.aligned.m8n8.x4.shared.b16 {%0,%1,%2,%3}, [%4];"
        : "=r"(r[0]), "=r"(r[1]), "=r"(r[2]), "=r"(r[3]) : "r"(addr));
}

__device__ __forceinline__ void mma_bf16(float* c, const uint32_t* a, const uint32_t* b) {
    asm volatile("mma.sync.aligned.m16n8k16.row.col.f32.bf16.bf16.f32 "
        "{%0,%1,%2,%3}, {%4,%5,%6,%7}, {%8,%9}, {%0,%1,%2,%3};"
        : "+f"(c[0]), "+f"(c[1]), "+f"(c[2]), "+f"(c[3])
        : "r"(a[0]), "r"(a[1]), "r"(a[2]), "r"(a[3]), "r"(b[0]), "r"(b[1]));
}

// ---------------- smem layout ----------------
// stage stride 40960B: Ah @0, Al @10240, Bh @20480, Bl @30720
// tile: 128 rows x 32 bf16, row stride 40 bf16 (80 B) -> conflict-free ldmatrix
#define TILE_B 10240
#define STAGE_B 40960
#define SMEMSZ (2 * STAGE_B)

__device__ __forceinline__ void load_stage(
    uint32_t base,
    const bf16* __restrict__ Ah, const bf16* __restrict__ Al,
    const bf16* __restrict__ Bh, const bf16* __restrict__ Bl,
    int rowBase, int colBase, int k0, int lda, int ldb, int tid)
{
    int lrow = tid >> 2, lc4 = tid & 3;
    #pragma unroll
    for (int r = 0; r < 2; r++) {
        int row = lrow + r * 64;
        uint32_t doff = row * 80 + lc4 * 16;
        int ke = k0 + lc4 * 8;
        CP_ASYNC16(base + 0 * TILE_B + doff, Ah + (long long)(rowBase + row) * lda + ke);
        CP_ASYNC16(base + 1 * TILE_B + doff, Al + (long long)(rowBase + row) * lda + ke);
        CP_ASYNC16(base + 2 * TILE_B + doff, Bh + (long long)(colBase + row) * ldb + ke);
        CP_ASYNC16(base + 3 * TILE_B + doff, Bl + (long long)(colBase + row) * ldb + ke);
    }
}

// ---------------- HMMA gemm core: one 128x128 fp32 C tile ----------------
__device__ void gemm_mma_core(
    const bf16* __restrict__ Ah, const bf16* __restrict__ Al,
    const bf16* __restrict__ Bh, const bf16* __restrict__ Bl,
    const float* __restrict__ bias, float* __restrict__ C,
    int rowBase, int colBase, int Klim,
    int lda, int ldb, int ldc, float alpha)
{
    extern __shared__ char smem[];
    uint32_t sb = smem_to_u32(smem);
    int tid = threadIdx.x, wid = tid >> 5, lane = tid & 31;
    int wm = wid & 1, wn = wid >> 1;

    // per-thread ldmatrix byte offsets within a tile
    uint32_t aoff = (lane & 15) * 80 + ((lane >= 16) ? 16 : 0);
    uint32_t boff = ((lane & 7) + ((lane >= 16) ? 8 : 0)) * 80 + (((lane >> 3) & 1) ? 16 : 0);

    float c[4][4][4];
    #pragma unroll
    for (int mi = 0; mi < 4; mi++)
        #pragma unroll
        for (int ni = 0; ni < 4; ni++)
            #pragma unroll
            for (int t = 0; t < 4; t++) c[mi][ni][t] = 0.f;

    int nst = Klim >> 5;
    load_stage(sb, Ah, Al, Bh, Bl, rowBase, colBase, 0, lda, ldb, tid);
    CP_COMMIT();

    for (int i = 0; i < nst; i++) {
        if (i + 1 < nst) {
            load_stage(sb + ((i + 1) & 1) * STAGE_B, Ah, Al, Bh, Bl,
                       rowBase, colBase, (i + 1) << 5, lda, ldb, tid);
            CP_COMMIT();
            asm volatile("cp.async.wait_group 1;" ::: "memory");
        } else {
            asm volatile("cp.async.wait_group 0;" ::: "memory");
        }
        __syncthreads();

        uint32_t base = sb + (i & 1) * STAGE_B;
        #pragma unroll
        for (int kk = 0; kk < 2; kk++) {
            uint32_t ah4[4][4], al4[4][4], bh4[2][4], bl4[2][4];
            #pragma unroll
            for (int mi = 0; mi < 4; mi++) {
                uint32_t ro = (64 * wm + 16 * mi) * 80 + kk * 32 + aoff;
                ldsm_x4(ah4[mi], base + 0 * TILE_B + ro);
                ldsm_x4(al4[mi], base + 1 * TILE_B + ro);
            }
            #pragma unroll
            for (int t = 0; t < 2; t++) {
                uint32_t ro = (32 * wn + 16 * t) * 80 + kk * 32 + boff;
                ldsm_x4(bh4[t], base + 2 * TILE_B + ro);
                ldsm_x4(bl4[t], base + 3 * TILE_B + ro);
            }
            #pragma unroll
            for (int mi = 0; mi < 4; mi++)
                #pragma unroll
                for (int ni = 0; ni < 4; ni++) {
                    uint32_t* bh = &bh4[ni >> 1][(ni & 1) * 2];
                    uint32_t* bl = &bl4[ni >> 1][(ni & 1) * 2];
                    mma_bf16(c[mi][ni], ah4[mi], bh);
                    mma_bf16(c[mi][ni], ah4[mi], bl);
                    mma_bf16(c[mi][ni], al4[mi], bh);
                }
        }
        __syncthreads();
    }

    // epilogue
    int g = lane >> 2, l4 = lane & 3;
    #pragma unroll
    for (int mi = 0; mi < 4; mi++)
        #pragma unroll
        for (int ni = 0; ni < 4; ni++) {
            int m = rowBase + 64 * wm + 16 * mi + g;
            int n = colBase + 32 * wn + 8 * ni + 2 * l4;
            float b0 = bias ? bias[n] : 0.f, b1 = bias ? bias[n + 1] : 0.f;
            float2 v0 = { c[mi][ni][0] * alpha + b0, c[mi][ni][1] * alpha + b1 };
            float2 v1 = { c[mi][ni][2] * alpha + b0, c[mi][ni][3] * alpha + b1 };
            *(float2*)&C[(long long)m * ldc + n] = v0;
            *(float2*)&C[(long long)(m + 8) * ldc + n] = v1;
        }
}

// ---------------- generic batched wrapper ----------------
__global__ __launch_bounds__(256) void gemm_mma(
    const bf16* Ah, const bf16* Al, const bf16* Bh, const bf16* Bl,
    const float* bias, float* C, int K, int lda, int ldb, int ldc,
    long long sA, long long sB, long long sC, int bDiv, float alpha, int causal)
{
    int bx = blockIdx.x, by = blockIdx.y, bz = blockIdx.z;
    if (causal == 1 && bx > by) return;
    int Klim = (causal == 2) ? min(K, (by + 1) * 128) : K;
    long long oA = (long long)bz * sA, oB = (long long)(bz / bDiv) * sB;
    gemm_mma_core(Ah + oA, Al + oA, Bh + oB, Bl + oB, bias, C + (long long)bz * sC,
                  by * 128, bx * 128, Klim, lda, ldb, ldc, alpha);
}

// ---------------- fused QKV ----------------
__global__ __launch_bounds__(256) void qkv_mma(
    const float* bq, const float* bk, const float* bv)
{
    int bx = blockIdx.x;
    const bf16 *Bh, *Bl; const float* bias; float* C; int ldc, cb;
    if (bx < 16)      { Bh = g_wqth; Bl = g_wqtl; bias = bq; C = g_qp; ldc = NH * HD;  cb = bx; }
    else if (bx < 18) { Bh = g_wkth; Bl = g_wktl; bias = bk; C = g_kp; ldc = NKV * HD; cb = bx - 16; }
    else              { Bh = g_wvth; Bl = g_wvtl; bias = bv; C = g_vp; ldc = NKV * HD; cb = bx - 18; }
    gemm_mma_core(g_hh, g_hl, Bh, Bl, bias, C, blockIdx.y * 128, cb * 128, HID,
                  HID, HID, ldc, 1.0f);
}

// ---------------- conversions ----------------
__global__ void conv_split(const float* __restrict__ in, bf16* oh, bf16* ol) {
    int i = blockIdx.x * 256 + threadIdx.x;
    float x = in[i];
    bf16 h = __float2bfloat16(x);
    oh[i] = h;
    ol[i] = __float2bfloat16(x - __bfloat162float(h));
}

// in [Kd][Nd] fp32 -> hi/lo [Nd][Kd] bf16
__global__ void transpose_split(const float* __restrict__ in, bf16* oh, bf16* ol,
                                int Kd, int Nd)
{
    __shared__ float t[32][33];
    int nb = blockIdx.x * 32, kb = blockIdx.y * 32;
    int x = threadIdx.x, y = threadIdx.y;
    #pragma unroll
    for (int r = 0; r < 32; r += 8)
        t[y + r][x] = in[(long long)(kb + y + r) * Nd + nb + x];
    __syncthreads();
    #pragma unroll
    for (int r = 0; r < 32; r += 8) {
        int n = nb + y + r, k = kb + x;
        float v = t[x][y + r];
        bf16 h = __float2bfloat16(v);
        oh[(long long)n * Kd + k] = h;
        ol[(long long)n * Kd + k] = __float2bfloat16(v - __bfloat162float(h));
    }
}

// ---------------- RoPE -> head-major bf16 splits ----------------
__global__ void rope_kernel(const float* __restrict__ cs, const float* __restrict__ sn)
{
    int idx = blockIdx.x * blockDim.x + threadIdx.x;
    int d = idx & (HD - 1);
    int s = (idx >> 7) & (S - 1);
    int h = idx >> 18;

    float c  = cs[(s << 7) + d];
    float si = sn[(s << 7) + d];
    if (h < NH) {
        const float* row = g_qp + (long long)s * (NH * HD) + h * HD;
        float x = row[d];
        float r = (d < 64) ? -row[d + 64] : row[d - 64];
        float val = x * c + r * si;
        long long o = ((long long)h * S + s) * HD + d;
        bf16 hh = __float2bfloat16(val);
        g_qh[o] = hh;
        g_ql[o] = __float2bfloat16(val - __bfloat162float(hh));
    } else {
        int hk = h - NH;
        const float* row = g_kp + (long long)s * (NKV * HD) + hk * HD;
        float x = row[d];
        float r = (d < 64) ? -row[d + 64] : row[d - 64];
        float val = x * c + r * si;
        long long o = ((long long)hk * S + s) * HD + d;
        bf16 hh = __float2bfloat16(val);
        g_kh[o] = hh;
        g_kl[o] = __float2bfloat16(val - __bfloat162float(hh));
    }
}

// ---------------- softmax: fp32 scores -> bf16 hi/lo probs (pad to 128) ----------------
__global__ __launch_bounds__(256) void softmax_kernel()
{
    int i = blockIdx.x, h = blockIdx.y;
    const float* row = g_sc + ((long long)h * S + i) * S;
    bf16* ph = g_ph + ((long long)h * S + i) * S;
    bf16* pl = g_pl + ((long long)h * S + i) * S;
    int L = i + 1, tid = threadIdx.x;
    __shared__ float red[256];

    float v[8];
    float m = -1e30f;
    int jj = 0;
    for (int j = tid; j < L; j += 256, jj++) { v[jj] = row[j]; m = fmaxf(m, v[jj]); }
    red[tid] = m; __syncthreads();
    for (int s2 = 128; s2 > 0; s2 >>= 1) {
        if (tid < s2) red[tid] = fmaxf(red[tid], red[tid + s2]);
        __syncthreads();
    }
    m = red[0]; __syncthreads();

    float sum = 0.f;
    jj = 0;
    for (int j = tid; j < L; j += 256, jj++) { v[jj] = __expf(v[jj] - m); sum += v[jj]; }
    red[tid] = sum; __syncthreads();
    for (int s2 = 128; s2 > 0; s2 >>= 1) {
        if (tid < s2) red[tid] += red[tid + s2];
        __syncthreads();
    }
    float inv = 1.0f / red[0];

    int Lpad = ((i >> 7) + 1) << 7;
    jj = 0;
    for (int j = tid; j < Lpad; j += 256, jj++) {
        float p = (j < L) ? v[jj] * inv : 0.f;
        bf16 hh = __float2bfloat16(p);
        ph[j] = hh;
        pl[j] = __float2bfloat16(p - __bfloat162float(hh));
    }
}

// ---------------- launch ----------------
extern "C" void kernel_launch(void* const* d_in, const int* in_sizes, int n_in,
                              void* d_out, int out_size)
{
    const float* hidden = (const float*)d_in[0];
    const float* cosb   = (const float*)d_in[1];
    const float* sinb   = (const float*)d_in[2];
    const float* Wq = (const float*)d_in[4];
    const float* bq = (const float*)d_in[5];
    const float* Wk = (const float*)d_in[6];
    const float* bk = (const float*)d_in[7];
    const float* Wv = (const float*)d_in[8];
    const float* bv = (const float*)d_in[9];
    const float* Wo = (const float*)d_in[10];
    float* out = (float*)d_out;

    cudaFuncSetAttribute(gemm_mma, cudaFuncAttributeMaxDynamicSharedMemorySize, SMEMSZ);
    cudaFuncSetAttribute(qkv_mma, cudaFuncAttributeMaxDynamicSharedMemorySize, SMEMSZ);

    bf16 *hh, *hl, *qh, *ql, *kh, *kl, *vth, *vtl, *phh, *pll, *aoh, *aol;
    float *qp, *kp, *vp, *sc, *ao;
    cudaGetSymbolAddress((void**)&hh, g_hh);   cudaGetSymbolAddress((void**)&hl, g_hl);
    cudaGetSymbolAddress((void**)&qp, g_qp);   cudaGetSymbolAddress((void**)&kp, g_kp);
    cudaGetSymbolAddress((void**)&vp, g_vp);   cudaGetSymbolAddress((void**)&sc, g_sc);
    cudaGetSymbolAddress((void**)&ao, g_ao);
    cudaGetSymbolAddress((void**)&qh, g_qh);   cudaGetSymbolAddress((void**)&ql, g_ql);
    cudaGetSymbolAddress((void**)&kh, g_kh);   cudaGetSymbolAddress((void**)&kl, g_kl);
    cudaGetSymbolAddress((void**)&vth, g_vth); cudaGetSymbolAddress((void**)&vtl, g_vtl);
    cudaGetSymbolAddress((void**)&phh, g_ph);  cudaGetSymbolAddress((void**)&pll, g_pl);
    cudaGetSymbolAddress((void**)&aoh, g_aoh); cudaGetSymbolAddress((void**)&aol, g_aol);

    bf16 *wqth, *wqtl, *wkth, *wktl, *wvth, *wvtl, *woth, *wotl;
    cudaGetSymbolAddress((void**)&wqth, g_wqth); cudaGetSymbolAddress((void**)&wqtl, g_wqtl);
    cudaGetSymbolAddress((void**)&wkth, g_wkth); cudaGetSymbolAddress((void**)&wktl, g_wktl);
    cudaGetSymbolAddress((void**)&wvth, g_wvth); cudaGetSymbolAddress((void**)&wvtl, g_wvtl);
    cudaGetSymbolAddress((void**)&woth, g_woth); cudaGetSymbolAddress((void**)&wotl, g_wotl);

    dim3 tb(32, 8);

    // 0) precision splits + weight transposes
    conv_split<<<S * HID / 256, 256>>>(hidden, hh, hl);
    transpose_split<<<dim3(HID / 32, HID / 32), tb>>>(Wq, wqth, wqtl, HID, HID);
    transpose_split<<<dim3(256 / 32, HID / 32), tb>>>(Wk, wkth, wktl, HID, 256);
    transpose_split<<<dim3(256 / 32, HID / 32), tb>>>(Wv, wvth, wvtl, HID, 256);
    transpose_split<<<dim3(HID / 32, HID / 32), tb>>>(Wo, woth, wotl, HID, HID);

    // 1) fused QKV projection
    qkv_mma<<<dim3(20, 16), 256, SMEMSZ>>>(bq, bk, bv);

    // 2) RoPE -> head-major bf16 splits
    rope_kernel<<<(NH + NKV) * S * HD / 256, 256>>>(cosb, sinb);

    // 2b) V^T split [NKV*HD][S]
    transpose_split<<<dim3(256 / 32, S / 32), tb>>>(vp, vth, vtl, S, 256);

    // 3) scores = scale * Q @ K^T (causal tile skip, GQA bDiv=8)
    gemm_mma<<<dim3(16, 16, NH), 256, SMEMSZ>>>(qh, ql, kh, kl, nullptr, sc,
        HD, HD, HD, S,
        (long long)S * HD, (long long)S * HD, (long long)S * S, NREP, SCALE, 1);

    // 4) softmax -> probs bf16 hi/lo
    softmax_kernel<<<dim3(S, NH), 256>>>();

    // 5) attn_out = P @ V (K clamped to causal tile end)
    gemm_mma<<<dim3(1, 16, NH), 256, SMEMSZ>>>(phh, pll, vth, vtl, nullptr, ao,
        S, S, S, NH * HD,
        (long long)S * S, (long long)HD * S, (long long)HD, NREP, 1.0f, 2);

    // 5b) split attn_out
    conv_split<<<S * HID / 256, 256>>>(ao, aoh, aol);

    // 6) output projection
    gemm_mma<<<dim3(16, 16, 1), 256, SMEMSZ>>>(aoh, aol, woth, wotl, nullptr, out,
        HID, HID, HID, HID, 0, 0, 0, 1, 1.0f, 0);
}

// round 6
// speedup vs baseline: 4.0433x; 1.4353x over previous
#include <cuda_runtime.h>
#include <cuda_bf16.h>
#include <cstdint>

typedef __nv_bfloat16 bf16;

#define S 2048
#define HID 2048
#define NH 16
#define NKV 2
#define HD 128
#define NREP 8
#define SCALE 0.08838834764831845f

// ---------------- scratch ----------------
__device__ __align__(16) bf16  g_hh[S * HID], g_hl[S * HID];
__device__ __align__(16) bf16  g_wqth[HID * HID], g_wqtl[HID * HID];   // W^T splits [N][K]
__device__ __align__(16) bf16  g_wkth[256 * HID], g_wktl[256 * HID];
__device__ __align__(16) bf16  g_wvth[256 * HID], g_wvtl[256 * HID];
__device__ __align__(16) bf16  g_woth[HID * HID], g_wotl[HID * HID];
__device__ float g_qp[S * NH * HD], g_kp[S * NKV * HD], g_vp[S * NKV * HD];
__device__ __align__(16) bf16  g_qh[NH * S * HD], g_ql[NH * S * HD];   // rope'd Q (pre-scaled)
__device__ __align__(16) bf16  g_kh[NKV * S * HD], g_kl[NKV * S * HD];
__device__ __align__(16) bf16  g_vth[NKV * HD * S], g_vtl[NKV * HD * S];  // V^T [D][S]
__device__ float g_ao[S * NH * HD];
__device__ __align__(16) bf16  g_aoh[S * NH * HD], g_aol[S * NH * HD];

// ---------------- PTX helpers ----------------
__device__ __forceinline__ uint32_t smem_to_u32(const void* p) {
    uint32_t a;
    asm("{ .reg .u64 t; cvta.to.shared.u64 t, %1; cvt.u32.u64 %0, t; }" : "=r"(a) : "l"(p));
    return a;
}
#define CP_ASYNC16(dst, src) \
    asm volatile("cp.async.cg.shared.global [%0], [%1], 16;" :: "r"(dst), "l"(src))
#define CP_COMMIT() asm volatile("cp.async.commit_group;" ::: "memory")
#define CP_WAIT1() asm volatile("cp.async.wait_group 1;" ::: "memory")
#define CP_WAIT0() asm volatile("cp.async.wait_group 0;" ::: "memory")

__device__ __forceinline__ void ldsm_x4(uint32_t* r, uint32_t addr) {
    asm volatile("ldmatrix.sync.aligned.m8n8.x4.shared.b16 {%0,%1,%2,%3}, [%4];"
        : "=r"(r[0]), "=r"(r[1]), "=r"(r[2]), "=r"(r[3]) : "r"(addr));
}
__device__ __forceinline__ void mma_bf16(float* c, const uint32_t* a, const uint32_t* b) {
    asm volatile("mma.sync.aligned.m16n8k16.row.col.f32.bf16.bf16.f32 "
        "{%0,%1,%2,%3}, {%4,%5,%6,%7}, {%8,%9}, {%0,%1,%2,%3};"
        : "+f"(c[0]), "+f"(c[1]), "+f"(c[2]), "+f"(c[3])
        : "r"(a[0]), "r"(a[1]), "r"(a[2]), "r"(a[3]), "r"(b[0]), "r"(b[1]));
}

// ============================================================================
// Dense GEMM path (QKV + output projection) — unchanged from R5
// ============================================================================
#define TILE_B 10240
#define STAGE_B 40960
#define SMEMSZ (2 * STAGE_B)

__device__ __forceinline__ void load_stage(
    uint32_t base,
    const bf16* __restrict__ Ah, const bf16* __restrict__ Al,
    const bf16* __restrict__ Bh, const bf16* __restrict__ Bl,
    int rowBase, int colBase, int k0, int lda, int ldb, int tid)
{
    int lrow = tid >> 2, lc4 = tid & 3;
    #pragma unroll
    for (int r = 0; r < 2; r++) {
        int row = lrow + r * 64;
        uint32_t doff = row * 80 + lc4 * 16;
        int ke = k0 + lc4 * 8;
        CP_ASYNC16(base + 0 * TILE_B + doff, Ah + (long long)(rowBase + row) * lda + ke);
        CP_ASYNC16(base + 1 * TILE_B + doff, Al + (long long)(rowBase + row) * lda + ke);
        CP_ASYNC16(base + 2 * TILE_B + doff, Bh + (long long)(colBase + row) * ldb + ke);
        CP_ASYNC16(base + 3 * TILE_B + doff, Bl + (long long)(colBase + row) * ldb + ke);
    }
}

__device__ void gemm_mma_core(
    const bf16* __restrict__ Ah, const bf16* __restrict__ Al,
    const bf16* __restrict__ Bh, const bf16* __restrict__ Bl,
    const float* __restrict__ bias, float* __restrict__ C,
    int rowBase, int colBase, int Klim,
    int lda, int ldb, int ldc, float alpha)
{
    extern __shared__ char smem[];
    uint32_t sb = smem_to_u32(smem);
    int tid = threadIdx.x, wid = tid >> 5, lane = tid & 31;
    int wm = wid & 1, wn = wid >> 1;

    uint32_t aoff = (lane & 15) * 80 + ((lane >= 16) ? 16 : 0);
    uint32_t boff = ((lane & 7) + ((lane >= 16) ? 8 : 0)) * 80 + (((lane >> 3) & 1) ? 16 : 0);

    float c[4][4][4];
    #pragma unroll
    for (int mi = 0; mi < 4; mi++)
        #pragma unroll
        for (int ni = 0; ni < 4; ni++)
            #pragma unroll
            for (int t = 0; t < 4; t++) c[mi][ni][t] = 0.f;

    int nst = Klim >> 5;
    load_stage(sb, Ah, Al, Bh, Bl, rowBase, colBase, 0, lda, ldb, tid);
    CP_COMMIT();

    for (int i = 0; i < nst; i++) {
        if (i + 1 < nst) {
            load_stage(sb + ((i + 1) & 1) * STAGE_B, Ah, Al, Bh, Bl,
                       rowBase, colBase, (i + 1) << 5, lda, ldb, tid);
            CP_COMMIT();
            CP_WAIT1();
        } else {
            CP_WAIT0();
        }
        __syncthreads();

        uint32_t base = sb + (i & 1) * STAGE_B;
        #pragma unroll
        for (int kk = 0; kk < 2; kk++) {
            uint32_t ah4[4][4], al4[4][4], bh4[2][4], bl4[2][4];
            #pragma unroll
            for (int mi = 0; mi < 4; mi++) {
                uint32_t ro = (64 * wm + 16 * mi) * 80 + kk * 32 + aoff;
                ldsm_x4(ah4[mi], base + 0 * TILE_B + ro);
                ldsm_x4(al4[mi], base + 1 * TILE_B + ro);
            }
            #pragma unroll
            for (int t = 0; t < 2; t++) {
                uint32_t ro = (32 * wn + 16 * t) * 80 + kk * 32 + boff;
                ldsm_x4(bh4[t], base + 2 * TILE_B + ro);
                ldsm_x4(bl4[t], base + 3 * TILE_B + ro);
            }
            #pragma unroll
            for (int mi = 0; mi < 4; mi++)
                #pragma unroll
                for (int ni = 0; ni < 4; ni++) {
                    uint32_t* bh = &bh4[ni >> 1][(ni & 1) * 2];
                    uint32_t* bl = &bl4[ni >> 1][(ni & 1) * 2];
                    mma_bf16(c[mi][ni], ah4[mi], bh);
                    mma_bf16(c[mi][ni], ah4[mi], bl);
                    mma_bf16(c[mi][ni], al4[mi], bh);
                }
        }
        __syncthreads();
    }

    int g = lane >> 2, l4 = lane & 3;
    #pragma unroll
    for (int mi = 0; mi < 4; mi++)
        #pragma unroll
        for (int ni = 0; ni < 4; ni++) {
            int m = rowBase + 64 * wm + 16 * mi + g;
            int n = colBase + 32 * wn + 8 * ni + 2 * l4;
            float b0 = bias ? bias[n] : 0.f, b1 = bias ? bias[n + 1] : 0.f;
            float2 v0 = { c[mi][ni][0] * alpha + b0, c[mi][ni][1] * alpha + b1 };
            float2 v1 = { c[mi][ni][2] * alpha + b0, c[mi][ni][3] * alpha + b1 };
            *(float2*)&C[(long long)m * ldc + n] = v0;
            *(float2*)&C[(long long)(m + 8) * ldc + n] = v1;
        }
}

__global__ __launch_bounds__(256) void gemm_mma(
    const bf16* Ah, const bf16* Al, const bf16* Bh, const bf16* Bl,
    const float* bias, float* C, int K, int lda, int ldb, int ldc, float alpha)
{
    gemm_mma_core(Ah, Al, Bh, Bl, bias, C,
                  blockIdx.y * 128, blockIdx.x * 128, K, lda, ldb, ldc, alpha);
}

__global__ __launch_bounds__(256) void qkv_mma(
    const float* bq, const float* bk, const float* bv)
{
    int bx = blockIdx.x;
    const bf16 *Bh, *Bl; const float* bias; float* C; int ldc, cb;
    if (bx < 16)      { Bh = g_wqth; Bl = g_wqtl; bias = bq; C = g_qp; ldc = NH * HD;  cb = bx; }
    else if (bx < 18) { Bh = g_wkth; Bl = g_wktl; bias = bk; C = g_kp; ldc = NKV * HD; cb = bx - 16; }
    else              { Bh = g_wvth; Bl = g_wvtl; bias = bv; C = g_vp; ldc = NKV * HD; cb = bx - 18; }
    gemm_mma_core(g_hh, g_hl, Bh, Bl, bias, C, blockIdx.y * 128, cb * 128, HID,
                  HID, HID, ldc, 1.0f);
}

// ============================================================================
// Flash attention kernel
// smem: Qh @0 (34816), Ql @34816; 2 KV bufs @69632, each 71680:
//   Kh @+0 (17408), Kl @+17408, Vh @+34816 (18432), Vl @+53248
// ============================================================================
#define FQH  0
#define FQL  34816
#define FKV  69632
#define FKVB 71680
#define FKL  17408
#define FVH  34816
#define FVL  53248
#define FSMEM (FKV + 2 * FKVB)

__device__ __forceinline__ void load_kv_tile(
    uint32_t dst, const bf16* __restrict__ Kh, const bf16* __restrict__ Kl,
    const bf16* __restrict__ Vh, const bf16* __restrict__ Vl, int j, int tid)
{
    // K tile: 64 rows x 128 bf16, smem stride 272B
    #pragma unroll
    for (int r = 0; r < 4; r++) {
        int idx = r * 256 + tid;
        int row = idx >> 4, c = idx & 15;
        uint32_t d = dst + row * 272 + c * 16;
        long long so = (long long)(j * 64 + row) * HD + c * 8;
        CP_ASYNC16(d, Kh + so);
        CP_ASYNC16(d + FKL, Kl + so);
    }
    // V^T tile: 128 rows (d) x 64 bf16 (seq), smem stride 144B
    #pragma unroll
    for (int r = 0; r < 4; r++) {
        int idx = r * 256 + tid;
        int row = idx >> 3, c = idx & 7;
        uint32_t d = dst + FVH + row * 144 + c * 16;
        long long so = (long long)row * S + j * 64 + c * 8;
        CP_ASYNC16(d, Vh + so);
        CP_ASYNC16(d + (FVL - FVH), Vl + so);
    }
}

__global__ __launch_bounds__(256, 1) void flash_kernel()
{
    int bx = blockIdx.x;
    int h = bx & 15, rb = 15 - (bx >> 4);
    int kvh = h >> 3;

    const bf16* Qh = g_qh + ((long long)h * S + rb * 128) * HD;
    const bf16* Ql = g_ql + ((long long)h * S + rb * 128) * HD;
    const bf16* Kh = g_kh + (long long)kvh * S * HD;
    const bf16* Kl = g_kl + (long long)kvh * S * HD;
    const bf16* Vh = g_vth + (long long)kvh * HD * S;
    const bf16* Vl = g_vtl + (long long)kvh * HD * S;

    extern __shared__ char smem[];
    uint32_t sb = smem_to_u32(smem);
    int tid = threadIdx.x, wid = tid >> 5, lane = tid & 31;
    int g = lane >> 2, l4 = lane & 3;

    // load Q (128 x 128 bf16 hi/lo), stride 272B
    #pragma unroll
    for (int r = 0; r < 8; r++) {
        int idx = r * 256 + tid;
        int row = idx >> 4, c = idx & 15;
        uint32_t d = row * 272 + c * 16;
        long long so = (long long)row * HD + c * 8;
        CP_ASYNC16(sb + FQH + d, Qh + so);
        CP_ASYNC16(sb + FQL + d, Ql + so);
    }
    int nt = 2 * (rb + 1);
    load_kv_tile(sb + FKV, Kh, Kl, Vh, Vl, 0, tid);
    CP_COMMIT();

    float o[16][4];
    #pragma unroll
    for (int n = 0; n < 16; n++)
        #pragma unroll
        for (int t = 0; t < 4; t++) o[n][t] = 0.f;
    float mrow0 = -1e30f, mrow1 = -1e30f, lrow0 = 0.f, lrow1 = 0.f;

    uint32_t aoff = (lane & 15) * 272 + ((lane >= 16) ? 16 : 0);
    uint32_t boff = ((lane & 7) + ((lane >= 16) ? 8 : 0)) * 272 + ((lane >> 3) & 1) * 16;
    uint32_t voff = ((lane & 7) + ((lane >= 16) ? 8 : 0)) * 144 + ((lane >> 3) & 1) * 16;
    uint32_t qa_h = sb + FQH + wid * (16 * 272) + aoff;
    uint32_t qa_l = sb + FQL + wid * (16 * 272) + aoff;

    int row0 = rb * 128 + wid * 16 + g;

    for (int j = 0; j < nt; j++) {
        if (j + 1 < nt) {
            load_kv_tile(sb + FKV + ((j + 1) & 1) * FKVB, Kh, Kl, Vh, Vl, j + 1, tid);
            CP_COMMIT();
            CP_WAIT1();
        } else {
            CP_WAIT0();
        }
        __syncthreads();
        uint32_t kb = sb + FKV + (j & 1) * FKVB;

        // ---- QK^T: scores 16x64 per warp ----
        float sc[8][4];
        #pragma unroll
        for (int n = 0; n < 8; n++)
            #pragma unroll
            for (int t = 0; t < 4; t++) sc[n][t] = 0.f;

        #pragma unroll
        for (int kt = 0; kt < 8; kt++) {
            uint32_t ah[4], al[4];
            ldsm_x4(ah, qa_h + kt * 32);
            ldsm_x4(al, qa_l + kt * 32);
            #pragma unroll
            for (int p = 0; p < 4; p++) {
                uint32_t bh[4], bl[4];
                ldsm_x4(bh, kb + boff + p * (16 * 272) + kt * 32);
                ldsm_x4(bl, kb + FKL + boff + p * (16 * 272) + kt * 32);
                mma_bf16(sc[2 * p],     ah, &bh[0]);
                mma_bf16(sc[2 * p],     ah, &bl[0]);
                mma_bf16(sc[2 * p],     al, &bh[0]);
                mma_bf16(sc[2 * p + 1], ah, &bh[2]);
                mma_bf16(sc[2 * p + 1], ah, &bl[2]);
                mma_bf16(sc[2 * p + 1], al, &bh[2]);
            }
        }

        // ---- causal mask (only last two tiles can cross the diagonal) ----
        if (j >= 2 * rb) {
            int colb = j * 64 + 2 * l4;
            #pragma unroll
            for (int n = 0; n < 8; n++) {
                int c0 = colb + 8 * n;
                if (c0 > row0)     sc[n][0] = -1e30f;
                if (c0 + 1 > row0) sc[n][1] = -1e30f;
                if (c0 > row0 + 8)     sc[n][2] = -1e30f;
                if (c0 + 1 > row0 + 8) sc[n][3] = -1e30f;
            }
        }

        // ---- online softmax ----
        float mt0 = -1e30f, mt1 = -1e30f;
        #pragma unroll
        for (int n = 0; n < 8; n++) {
            mt0 = fmaxf(mt0, fmaxf(sc[n][0], sc[n][1]));
            mt1 = fmaxf(mt1, fmaxf(sc[n][2], sc[n][3]));
        }
        mt0 = fmaxf(mt0, __shfl_xor_sync(0xffffffff, mt0, 1));
        mt0 = fmaxf(mt0, __shfl_xor_sync(0xffffffff, mt0, 2));
        mt1 = fmaxf(mt1, __shfl_xor_sync(0xffffffff, mt1, 1));
        mt1 = fmaxf(mt1, __shfl_xor_sync(0xffffffff, mt1, 2));
        float mnew0 = fmaxf(mrow0, mt0), mnew1 = fmaxf(mrow1, mt1);
        float cf0 = __expf(mrow0 - mnew0), cf1 = __expf(mrow1 - mnew1);
        mrow0 = mnew0; mrow1 = mnew1;

        uint32_t pah[4][4], pal[4][4];
        float rs0 = 0.f, rs1 = 0.f;
        #pragma unroll
        for (int t = 0; t < 4; t++) {
            #pragma unroll
            for (int e = 0; e < 2; e++) {
                int n = 2 * t + e;
                float p0 = __expf(sc[n][0] - mnew0);
                float p1 = __expf(sc[n][1] - mnew0);
                float p2 = __expf(sc[n][2] - mnew1);
                float p3 = __expf(sc[n][3] - mnew1);
                rs0 += p0 + p1; rs1 += p2 + p3;
                __nv_bfloat162 h01 = __floats2bfloat162_rn(p0, p1);
                __nv_bfloat162 h23 = __floats2bfloat162_rn(p2, p3);
                __nv_bfloat162 l01 = __floats2bfloat162_rn(p0 - __low2float(h01),
                                                           p1 - __high2float(h01));
                __nv_bfloat162 l23 = __floats2bfloat162_rn(p2 - __low2float(h23),
                                                           p3 - __high2float(h23));
                pah[t][2 * e]     = *(uint32_t*)&h01;
                pah[t][2 * e + 1] = *(uint32_t*)&h23;
                pal[t][2 * e]     = *(uint32_t*)&l01;
                pal[t][2 * e + 1] = *(uint32_t*)&l23;
            }
        }
        lrow0 = lrow0 * cf0 + rs0;
        lrow1 = lrow1 * cf1 + rs1;

        #pragma unroll
        for (int n = 0; n < 16; n++) {
            o[n][0] *= cf0; o[n][1] *= cf0;
            o[n][2] *= cf1; o[n][3] *= cf1;
        }

        // ---- P @ V ----
        #pragma unroll
        for (int p = 0; p < 8; p++) {
            #pragma unroll
            for (int t = 0; t < 4; t++) {
                uint32_t vh[4], vl[4];
                ldsm_x4(vh, kb + FVH + voff + p * (16 * 144) + t * 32);
                ldsm_x4(vl, kb + FVL + voff + p * (16 * 144) + t * 32);
                mma_bf16(o[2 * p],     pah[t], &vh[0]);
                mma_bf16(o[2 * p],     pal[t], &vh[0]);
                mma_bf16(o[2 * p],     pah[t], &vl[0]);
                mma_bf16(o[2 * p + 1], pah[t], &vh[2]);
                mma_bf16(o[2 * p + 1], pal[t], &vh[2]);
                mma_bf16(o[2 * p + 1], pah[t], &vl[2]);
            }
        }
        __syncthreads();
    }

    // final: reduce row sums across quad, divide, write
    float ls0 = lrow0 + __shfl_xor_sync(0xffffffff, lrow0, 1);
    ls0 += __shfl_xor_sync(0xffffffff, ls0, 2);
    float ls1 = lrow1 + __shfl_xor_sync(0xffffffff, lrow1, 1);
    ls1 += __shfl_xor_sync(0xffffffff, ls1, 2);
    float inv0 = 1.0f / ls0, inv1 = 1.0f / ls1;

    #pragma unroll
    for (int n = 0; n < 16; n++) {
        int col = h * HD + n * 8 + 2 * l4;
        float2 v0 = { o[n][0] * inv0, o[n][1] * inv0 };
        float2 v1 = { o[n][2] * inv1, o[n][3] * inv1 };
        *(float2*)&g_ao[(long long)row0 * (NH * HD) + col] = v0;
        *(float2*)&g_ao[(long long)(row0 + 8) * (NH * HD) + col] = v1;
    }
}

// ---------------- conversions ----------------
__global__ void conv_split(const float* __restrict__ in, bf16* oh, bf16* ol) {
    int i = blockIdx.x * 256 + threadIdx.x;
    float x = in[i];
    bf16 h = __float2bfloat16(x);
    oh[i] = h;
    ol[i] = __float2bfloat16(x - __bfloat162float(h));
}

__global__ void transpose_split(const float* __restrict__ in, bf16* oh, bf16* ol,
                                int Kd, int Nd)
{
    __shared__ float t[32][33];
    int nb = blockIdx.x * 32, kb = blockIdx.y * 32;
    int x = threadIdx.x, y = threadIdx.y;
    #pragma unroll
    for (int r = 0; r < 32; r += 8)
        t[y + r][x] = in[(long long)(kb + y + r) * Nd + nb + x];
    __syncthreads();
    #pragma unroll
    for (int r = 0; r < 32; r += 8) {
        int n = nb + y + r, k = kb + x;
        float v = t[x][y + r];
        bf16 h = __float2bfloat16(v);
        oh[(long long)n * Kd + k] = h;
        ol[(long long)n * Kd + k] = __float2bfloat16(v - __bfloat162float(h));
    }
}

// ---------------- RoPE -> head-major bf16 splits (Q pre-scaled) ----------------
__global__ void rope_kernel(const float* __restrict__ cs, const float* __restrict__ sn)
{
    int idx = blockIdx.x * blockDim.x + threadIdx.x;
    int d = idx & (HD - 1);
    int s = (idx >> 7) & (S - 1);
    int h = idx >> 18;

    float c  = cs[(s << 7) + d];
    float si = sn[(s << 7) + d];
    if (h < NH) {
        const float* row = g_qp + (long long)s * (NH * HD) + h * HD;
        float x = row[d];
        float r = (d < 64) ? -row[d + 64] : row[d - 64];
        float val = (x * c + r * si) * SCALE;
        long long o = ((long long)h * S + s) * HD + d;
        bf16 hh = __float2bfloat16(val);
        g_qh[o] = hh;
        g_ql[o] = __float2bfloat16(val - __bfloat162float(hh));
    } else {
        int hk = h - NH;
        const float* row = g_kp + (long long)s * (NKV * HD) + hk * HD;
        float x = row[d];
        float r = (d < 64) ? -row[d + 64] : row[d - 64];
        float val = x * c + r * si;
        long long o = ((long long)hk * S + s) * HD + d;
        bf16 hh = __float2bfloat16(val);
        g_kh[o] = hh;
        g_kl[o] = __float2bfloat16(val - __bfloat162float(hh));
    }
}

// ---------------- launch ----------------
extern "C" void kernel_launch(void* const* d_in, const int* in_sizes, int n_in,
                              void* d_out, int out_size)
{
    const float* hidden = (const float*)d_in[0];
    const float* cosb   = (const float*)d_in[1];
    const float* sinb   = (const float*)d_in[2];
    const float* Wq = (const float*)d_in[4];
    const float* bq = (const float*)d_in[5];
    const float* Wk = (const float*)d_in[6];
    const float* bk = (const float*)d_in[7];
    const float* Wv = (const float*)d_in[8];
    const float* bv = (const float*)d_in[9];
    const float* Wo = (const float*)d_in[10];
    float* out = (float*)d_out;

    cudaFuncSetAttribute(gemm_mma, cudaFuncAttributeMaxDynamicSharedMemorySize, SMEMSZ);
    cudaFuncSetAttribute(qkv_mma, cudaFuncAttributeMaxDynamicSharedMemorySize, SMEMSZ);
    cudaFuncSetAttribute(flash_kernel, cudaFuncAttributeMaxDynamicSharedMemorySize, FSMEM);

    bf16 *hh, *hl, *vth, *vtl, *aoh, *aol;
    float *vp, *ao;
    cudaGetSymbolAddress((void**)&hh, g_hh);   cudaGetSymbolAddress((void**)&hl, g_hl);
    cudaGetSymbolAddress((void**)&vp, g_vp);   cudaGetSymbolAddress((void**)&ao, g_ao);
    cudaGetSymbolAddress((void**)&vth, g_vth); cudaGetSymbolAddress((void**)&vtl, g_vtl);
    cudaGetSymbolAddress((void**)&aoh, g_aoh); cudaGetSymbolAddress((void**)&aol, g_aol);

    bf16 *wqth, *wqtl, *wkth, *wktl, *wvth, *wvtl, *woth, *wotl;
    cudaGetSymbolAddress((void**)&wqth, g_wqth); cudaGetSymbolAddress((void**)&wqtl, g_wqtl);
    cudaGetSymbolAddress((void**)&wkth, g_wkth); cudaGetSymbolAddress((void**)&wktl, g_wktl);
    cudaGetSymbolAddress((void**)&wvth, g_wvth); cudaGetSymbolAddress((void**)&wvtl, g_wvtl);
    cudaGetSymbolAddress((void**)&woth, g_woth); cudaGetSymbolAddress((void**)&wotl, g_wotl);

    dim3 tb(32, 8);

    // 0) precision splits + weight transposes
    conv_split<<<S * HID / 256, 256>>>(hidden, hh, hl);
    transpose_split<<<dim3(HID / 32, HID / 32), tb>>>(Wq, wqth, wqtl, HID, HID);
    transpose_split<<<dim3(256 / 32, HID / 32), tb>>>(Wk, wkth, wktl, HID, 256);
    transpose_split<<<dim3(256 / 32, HID / 32), tb>>>(Wv, wvth, wvtl, HID, 256);
    transpose_split<<<dim3(HID / 32, HID / 32), tb>>>(Wo, woth, wotl, HID, HID);

    // 1) fused QKV projection
    qkv_mma<<<dim3(20, 16), 256, SMEMSZ>>>(bq, bk, bv);

    // 2) RoPE -> head-major bf16 splits (Q pre-scaled by 1/sqrt(D))
    rope_kernel<<<(NH + NKV) * S * HD / 256, 256>>>(cosb, sinb);

    // 2b) V^T split [NKV*HD][S]
    transpose_split<<<dim3(256 / 32, S / 32), tb>>>(vp, vth, vtl, S, 256);

    // 3) flash attention (fused scores + softmax + PV)
    flash_kernel<<<256, 256, FSMEM>>>();

    // 4) split attn_out
    conv_split<<<S * HID / 256, 256>>>(ao, aoh, aol);

    // 5) output projection
    gemm_mma<<<dim3(16, 16), 256, SMEMSZ>>>(aoh, aol, woth, wotl, nullptr, out,
        HID, HID, HID, HID, 1.0f);
}